// round 12
// baseline (speedup 1.0000x reference)
#include <cuda_runtime.h>
#include <math.h>
#include <stdint.h>

// ---------------- problem constants ----------------
#define NMAX 50000
#define EMAX 800000
#define D 128
#define HMAX 384

// ---------------- scratch (device globals; no mallocs allowed) ----------------
__device__ float g_h [NMAX * D];
__device__ float g_hn[NMAX * D];
__device__ float g_xl[NMAX * D];
__device__ float g_xr[NMAX * D];
__device__ float g_hid[NMAX * HMAX];
__device__ int   g_cnt[NMAX];
__device__ int   g_row[NMAX];
__device__ int   g_cur[NMAX];
__device__ int   g_csr_src[EMAX];
__device__ int   g_partial[256];
__device__ float g_pool_s[NMAX];
__device__ float g_hp[D];
__device__ float g_sumw;
__device__ unsigned g_maxu;

// ---------------- helpers ----------------
__device__ __forceinline__ unsigned fenc(float f) {
    unsigned b = __float_as_uint(f);
    return (b & 0x80000000u) ? ~b : (b | 0x80000000u);
}
__device__ __forceinline__ float fdec(unsigned u) {
    return __uint_as_float((u & 0x80000000u) ? (u & 0x7FFFFFFFu) : ~u);
}
__device__ __forceinline__ uint32_t f2tf(float f) {
    uint32_t u;
    asm("cvt.rna.tf32.f32 %0, %1;" : "=r"(u) : "f"(f));
    return u;
}

#define ACT_NONE 0
#define ACT_RELU 1
#define ACT_GELU 2
#define ACT_TANH 3
#define ACT_SIGM 4

__device__ __forceinline__ float apply_act(float v, int act) {
    switch (act) {
        case ACT_RELU: return v > 0.f ? v : 0.f;
        case ACT_GELU: return 0.5f * v * (1.f + erff(v * 0.70710678118654752f));
        case ACT_TANH: return tanhf(v);
        case ACT_SIGM: return 1.f / (1.f + expf(-v));
        default: return v;
    }
}

// ---------------- CSR build (round-4 version: NO self loop in CSR) ----------------
__global__ void csr_zero_kernel(int n) {
    int i = blockIdx.x * blockDim.x + threadIdx.x;
    if (i < n) g_cnt[i] = 0;
}
__global__ void csr_count_kernel(const int* __restrict__ ei, int E) {
    int i = blockIdx.x * blockDim.x + threadIdx.x;
    if (i < E) atomicAdd(&g_cnt[ei[E + i]], 1);
}
__global__ void scan1_kernel(int n) {
    __shared__ int sm[256];
    int t = threadIdx.x;
    int i = blockIdx.x * 256 + t;
    int v = (i < n) ? g_cnt[i] : 0;
    sm[t] = v;
    __syncthreads();
#pragma unroll
    for (int off = 1; off < 256; off <<= 1) {
        int a = (t >= off) ? sm[t - off] : 0;
        __syncthreads();
        sm[t] += a;
        __syncthreads();
    }
    if (i < n) g_row[i] = sm[t] - v;   // exclusive
    if (t == 255) g_partial[blockIdx.x] = sm[255];
}
__global__ void scan2_kernel(int nb) {
    __shared__ int sm[256];
    int t = threadIdx.x;
    int v = (t < nb) ? g_partial[t] : 0;
    sm[t] = v;
    __syncthreads();
#pragma unroll
    for (int off = 1; off < 256; off <<= 1) {
        int a = (t >= off) ? sm[t - off] : 0;
        __syncthreads();
        sm[t] += a;
        __syncthreads();
    }
    if (t < nb) g_partial[t] = sm[t] - v;  // exclusive
}
__global__ void scan3_kernel(int n) {
    int i = blockIdx.x * blockDim.x + threadIdx.x;
    if (i < n) {
        int v = g_row[i] + g_partial[i >> 8];
        g_row[i] = v;
        g_cur[i] = v;
    }
}
__global__ void csr_scatter_kernel(const int* __restrict__ ei, int E) {
    int i = blockIdx.x * blockDim.x + threadIdx.x;
    if (i < E) {
        int d = ei[E + i];
        int slot = atomicAdd(&g_cur[d], 1);
        g_csr_src[slot] = ei[i];
    }
}

// ---------------- init ----------------
__global__ void init_pool_kernel() {
    int t = threadIdx.x;
    g_hp[t] = 0.f;
    if (t == 0) { g_sumw = 0.f; g_maxu = 0u; }
}

// ---------------- tf32 tensor-core GEMM (optional 2nd problem sharing A via blockIdx.z) ----------------
__global__ __launch_bounds__(256, 2)
void tgemm_kernel(const float* __restrict__ A,
                  const float* __restrict__ B,  const float* __restrict__ bias,
                  float* __restrict__ C,  int act,
                  const float* __restrict__ B2, const float* __restrict__ bias2,
                  float* __restrict__ C2, int act2,
                  int n, int K, int M, int residual)
{
    __shared__ uint32_t sA[128][36];
    __shared__ uint32_t sB[32][136];

    if (blockIdx.z == 1) { B = B2; bias = bias2; C = C2; act = act2; }

    int tid  = threadIdx.x;
    int lane = tid & 31;
    int warp = tid >> 5;
    int g    = lane >> 2;
    int tig  = lane & 3;
    int mW   = (warp & 3) * 32;
    int nW   = (warp >> 2) * 64;
    int rowBase = blockIdx.x * 128;
    int colBase = blockIdx.y * 128;

    float acc[2][8][4];
#pragma unroll
    for (int mt = 0; mt < 2; mt++)
#pragma unroll
        for (int nt = 0; nt < 8; nt++)
#pragma unroll
            for (int c = 0; c < 4; c++) acc[mt][nt][c] = 0.f;

    for (int k0 = 0; k0 < K; k0 += 32) {
#pragma unroll
        for (int i = 0; i < 4; i++) {
            int idx = tid + 256 * i;
            int r   = idx >> 3;
            int kc  = (idx & 7) * 4;
            int gr  = rowBase + r;
            float4 v = make_float4(0.f, 0.f, 0.f, 0.f);
            if (gr < n) v = *reinterpret_cast<const float4*>(A + (size_t)gr * K + k0 + kc);
            sA[r][kc + 0] = f2tf(v.x);
            sA[r][kc + 1] = f2tf(v.y);
            sA[r][kc + 2] = f2tf(v.z);
            sA[r][kc + 3] = f2tf(v.w);
        }
#pragma unroll
        for (int i = 0; i < 4; i++) {
            int idx = tid + 256 * i;
            int kr  = idx >> 5;
            int c   = (idx & 31) * 4;
            float4 v = *reinterpret_cast<const float4*>(B + (size_t)(k0 + kr) * M + colBase + c);
            sB[kr][c + 0] = f2tf(v.x);
            sB[kr][c + 1] = f2tf(v.y);
            sB[kr][c + 2] = f2tf(v.z);
            sB[kr][c + 3] = f2tf(v.w);
        }
        __syncthreads();

#pragma unroll
        for (int kt = 0; kt < 4; kt++) {
            int kb = kt * 8;
            uint32_t a[2][4], b[8][2];
#pragma unroll
            for (int mt = 0; mt < 2; mt++) {
                int mb = mW + mt * 16;
                a[mt][0] = sA[mb + g    ][kb + tig    ];
                a[mt][1] = sA[mb + g + 8][kb + tig    ];
                a[mt][2] = sA[mb + g    ][kb + tig + 4];
                a[mt][3] = sA[mb + g + 8][kb + tig + 4];
            }
#pragma unroll
            for (int nt = 0; nt < 8; nt++) {
                int nb = nW + nt * 8;
                b[nt][0] = sB[kb + tig    ][nb + g];
                b[nt][1] = sB[kb + tig + 4][nb + g];
            }
#pragma unroll
            for (int mt = 0; mt < 2; mt++)
#pragma unroll
                for (int nt = 0; nt < 8; nt++) {
                    asm volatile(
                        "mma.sync.aligned.m16n8k8.row.col.f32.tf32.tf32.f32 "
                        "{%0,%1,%2,%3}, {%4,%5,%6,%7}, {%8,%9}, {%0,%1,%2,%3};"
                        : "+f"(acc[mt][nt][0]), "+f"(acc[mt][nt][1]),
                          "+f"(acc[mt][nt][2]), "+f"(acc[mt][nt][3])
                        : "r"(a[mt][0]), "r"(a[mt][1]), "r"(a[mt][2]), "r"(a[mt][3]),
                          "r"(b[nt][0]), "r"(b[nt][1]));
                }
        }
        __syncthreads();
    }

#pragma unroll
    for (int mt = 0; mt < 2; mt++) {
#pragma unroll
        for (int half = 0; half < 2; half++) {
            int gr = rowBase + mW + mt * 16 + g + half * 8;
            if (gr >= n) continue;
#pragma unroll
            for (int nt = 0; nt < 8; nt++) {
#pragma unroll
                for (int j = 0; j < 2; j++) {
                    int gc = colBase + nW + nt * 8 + tig * 2 + j;
                    float v = acc[mt][nt][half * 2 + j];
                    if (bias) v += bias[gc];
                    v = apply_act(v, act);
                    size_t o = (size_t)gr * M + gc;
                    if (residual) C[o] = C[o] + v; else C[o] = v;
                }
            }
        }
    }
}

// ---------------- LayerNorm (warp per row, float4) ----------------
__global__ void ln_kernel(const float* __restrict__ X, const float* __restrict__ g,
                          const float* __restrict__ b, float* __restrict__ Y, int n)
{
    int w = (blockIdx.x * blockDim.x + threadIdx.x) >> 5;
    int lane = threadIdx.x & 31;
    if (w >= n) return;
    float4 v = reinterpret_cast<const float4*>(X + (size_t)w * D)[lane];
    float s  = v.x + v.y + v.z + v.w;
    float s2 = v.x * v.x + v.y * v.y + v.z * v.z + v.w * v.w;
#pragma unroll
    for (int off = 16; off > 0; off >>= 1) {
        s  += __shfl_xor_sync(0xFFFFFFFFu, s,  off);
        s2 += __shfl_xor_sync(0xFFFFFFFFu, s2, off);
    }
    float mu = s * (1.f / 128.f);
    float var = s2 * (1.f / 128.f) - mu * mu;
    float rstd = rsqrtf(var + 1e-5f);
    float4 gg = reinterpret_cast<const float4*>(g)[lane];
    float4 bb = reinterpret_cast<const float4*>(b)[lane];
    float4 o;
    o.x = (v.x - mu) * rstd * gg.x + bb.x;
    o.y = (v.y - mu) * rstd * gg.y + bb.y;
    o.z = (v.z - mu) * rstd * gg.z + bb.z;
    o.w = (v.w - mu) * rstd * gg.w + bb.w;
    reinterpret_cast<float4*>(Y + (size_t)w * D)[lane] = o;
}

// ---------------- GATv2 fused: warp per node, online softmax, no atomics (round-4 body) ----------------
__global__ void gat_gather_kernel(const float* __restrict__ xl, const float* __restrict__ xr,
                                  const float* __restrict__ att, const float* __restrict__ bias,
                                  int n)
{
    int node = (blockIdx.x * blockDim.x + threadIdx.x) >> 5;
    int lane = threadIdx.x & 31;
    if (node >= n) return;

    float4 at4 = reinterpret_cast<const float4*>(att)[lane];
    float4 xr4 = reinterpret_cast<const float4*>(xr + (size_t)node * D)[lane];

    // self loop first (appended self loops in reference) — handled ONLY here,
    // the CSR contains no self loops.
    float4 v4 = reinterpret_cast<const float4*>(xl + (size_t)node * D)[lane];
    float ex, ey, ez, ew, sc;
    {
        ex = v4.x + xr4.x; ex = ex > 0.f ? ex : 0.2f * ex;
        ey = v4.y + xr4.y; ey = ey > 0.f ? ey : 0.2f * ey;
        ez = v4.z + xr4.z; ez = ez > 0.f ? ez : 0.2f * ez;
        ew = v4.w + xr4.w; ew = ew > 0.f ? ew : 0.2f * ew;
        sc = ex * at4.x + ey * at4.y + ez * at4.z + ew * at4.w;
#pragma unroll
        for (int off = 16; off > 0; off >>= 1) sc += __shfl_xor_sync(0xFFFFFFFFu, sc, off);
    }
    float m = sc;
    float den = 1.f;
    float4 acc = v4;   // weight exp(sc - m) = 1

    int beg = g_row[node];
    int end = beg + g_cnt[node];
    for (int j = beg; j < end; j++) {
        int s = g_csr_src[j];
        v4 = reinterpret_cast<const float4*>(xl + (size_t)s * D)[lane];
        ex = v4.x + xr4.x; ex = ex > 0.f ? ex : 0.2f * ex;
        ey = v4.y + xr4.y; ey = ey > 0.f ? ey : 0.2f * ey;
        ez = v4.z + xr4.z; ez = ez > 0.f ? ez : 0.2f * ez;
        ew = v4.w + xr4.w; ew = ew > 0.f ? ew : 0.2f * ew;
        sc = ex * at4.x + ey * at4.y + ez * at4.z + ew * at4.w;
#pragma unroll
        for (int off = 16; off > 0; off >>= 1) sc += __shfl_xor_sync(0xFFFFFFFFu, sc, off);
        if (sc > m) {
            float f = expf(m - sc);
            den *= f;
            acc.x *= f; acc.y *= f; acc.z *= f; acc.w *= f;
            m = sc;
        }
        float w = expf(sc - m);
        den += w;
        acc.x += w * v4.x; acc.y += w * v4.y; acc.z += w * v4.z; acc.w += w * v4.w;
    }

    float inv = 1.f / den;
    float4 bb = reinterpret_cast<const float4*>(bias)[lane];
    float4* hp = reinterpret_cast<float4*>(g_h + (size_t)node * D);
    float4 h = hp[lane];
    h.x += acc.x * inv + bb.x;
    h.y += acc.y * inv + bb.y;
    h.z += acc.z * inv + bb.z;
    h.w += acc.w * inv + bb.w;
    hp[lane] = h;
}

// ---------------- pooling ----------------
__global__ void pool_score_kernel(const float* __restrict__ ta, const float* __restrict__ tb,
                                  const float* __restrict__ Wc, const float* __restrict__ bc, int n)
{
    int w = (blockIdx.x * blockDim.x + threadIdx.x) >> 5;
    int lane = threadIdx.x & 31;
    if (w >= n) return;
    float4 a = reinterpret_cast<const float4*>(ta + (size_t)w * D)[lane];
    float4 b = reinterpret_cast<const float4*>(tb + (size_t)w * D)[lane];
    float4 c = reinterpret_cast<const float4*>(Wc)[lane];
    float acc = a.x * b.x * c.x + a.y * b.y * c.y + a.z * b.z * c.z + a.w * b.w * c.w;
#pragma unroll
    for (int off = 16; off > 0; off >>= 1) acc += __shfl_xor_sync(0xFFFFFFFFu, acc, off);
    if (lane == 0) g_pool_s[w] = acc + bc[0];
}

__global__ void pool_max_kernel(int n)
{
    __shared__ float sm[256];
    int t = threadIdx.x;
    float m = -1e30f;
    for (int i = blockIdx.x * blockDim.x + t; i < n; i += gridDim.x * blockDim.x)
        m = fmaxf(m, g_pool_s[i]);
    sm[t] = m;
    __syncthreads();
    for (int s = 128; s > 0; s >>= 1) {
        if (t < s) sm[t] = fmaxf(sm[t], sm[t + s]);
        __syncthreads();
    }
    if (t == 0) atomicMax(&g_maxu, fenc(sm[0]));
}

__global__ void pool_accum_kernel(int n)
{
    __shared__ float sacc[D];
    int t = threadIdx.x;
    int lane = t & 31;
    if (t < D) sacc[t] = 0.f;
    __syncthreads();
    float mx = fdec(g_maxu);
    float4 racc = make_float4(0.f, 0.f, 0.f, 0.f);
    float wsum = 0.f;
    int nwarps = (gridDim.x * blockDim.x) >> 5;
    for (int nd = (blockIdx.x * blockDim.x + t) >> 5; nd < n; nd += nwarps) {
        float w = expf(g_pool_s[nd] - mx);
        if (lane == 0) wsum += w;
        float4 v = reinterpret_cast<const float4*>(g_h + (size_t)nd * D)[lane];
        racc.x += w * v.x; racc.y += w * v.y; racc.z += w * v.z; racc.w += w * v.w;
    }
    atomicAdd(&sacc[lane * 4 + 0], racc.x);
    atomicAdd(&sacc[lane * 4 + 1], racc.y);
    atomicAdd(&sacc[lane * 4 + 2], racc.z);
    atomicAdd(&sacc[lane * 4 + 3], racc.w);
    __syncthreads();
    if (t < D) atomicAdd(&g_hp[t], sacc[t]);
    if (lane == 0 && wsum != 0.f) atomicAdd(&g_sumw, wsum);
}

// ---------------- final head ----------------
__global__ void final_kernel(const float* __restrict__ rho_W, const float* __restrict__ rho_b,
                             const float* __restrict__ cls_W, const float* __restrict__ cls_b,
                             float* __restrict__ out)
{
    __shared__ float hp[D];
    __shared__ float hr[D];
    __shared__ float slog[4];
    int t = threadIdx.x;
    hp[t] = g_hp[t] / g_sumw;
    __syncthreads();
    float a = rho_b[t];
#pragma unroll 4
    for (int k = 0; k < D; k++) a += hp[k] * rho_W[k * D + t];
    hr[t] = a > 0.f ? a : 0.f;
    __syncthreads();
    if (t < 4) {
        float lg = cls_b[t];
#pragma unroll 4
        for (int d = 0; d < D; d++) lg += hr[d] * cls_W[d * 4 + t];
        slog[t] = lg;
    }
    __syncthreads();
    if (t == 0) {
        float hz[4], S[4];
        int am = 0;
        float best = slog[0];
        for (int c = 0; c < 4; c++) {
            hz[c] = 1.f / (1.f + expf(-slog[c]));
            if (slog[c] > best) { best = slog[c]; am = c; }
        }
        S[0] = 1.f - hz[0];
        for (int c = 1; c < 4; c++) S[c] = S[c - 1] * (1.f - hz[c]);
        for (int c = 0; c < 4; c++) out[c] = hz[c];
        for (int c = 0; c < 4; c++) out[4 + c] = S[c];
        out[8] = (float)am;
        for (int c = 0; c < 4; c++) out[9 + c] = slog[c];
    }
}

// ---------------- launch ----------------
extern "C" void kernel_launch(void* const* d_in, const int* in_sizes, int n_in,
                              void* d_out, int out_size)
{
    const float* x      = (const float*)d_in[0];
    const int*   ei     = (const int*)d_in[1];
    const float* emb_W  = (const float*)d_in[2];
    const float* emb_b  = (const float*)d_in[3];
    const float* ln1_g  = (const float*)d_in[4];
    const float* ln1_b  = (const float*)d_in[5];
    const float* gat_Wl = (const float*)d_in[6];
    const float* gat_bl = (const float*)d_in[7];
    const float* gat_Wr = (const float*)d_in[8];
    const float* gat_br = (const float*)d_in[9];
    const float* gat_att  = (const float*)d_in[10];
    const float* gat_bias = (const float*)d_in[11];
    const float* w1s[3] = {(const float*)d_in[12], (const float*)d_in[14], (const float*)d_in[16]};
    const float* w2s[3] = {(const float*)d_in[13], (const float*)d_in[15], (const float*)d_in[17]};
    const float* attn_Wa = (const float*)d_in[18];
    const float* attn_ba = (const float*)d_in[19];
    const float* attn_Wb = (const float*)d_in[20];
    const float* attn_bb = (const float*)d_in[21];
    const float* attn_Wc = (const float*)d_in[22];
    const float* attn_bc = (const float*)d_in[23];
    const float* rho_W   = (const float*)d_in[24];
    const float* rho_b   = (const float*)d_in[25];
    const float* cls_W   = (const float*)d_in[26];
    const float* cls_b   = (const float*)d_in[27];
    float* out = (float*)d_out;

    int n  = in_sizes[0] / 512;     // 50000
    int E  = in_sizes[1] / 2;       // 800000

    float* p_h;    cudaGetSymbolAddress((void**)&p_h,    g_h);
    float* p_hn;   cudaGetSymbolAddress((void**)&p_hn,   g_hn);
    float* p_xl;   cudaGetSymbolAddress((void**)&p_xl,   g_xl);
    float* p_xr;   cudaGetSymbolAddress((void**)&p_xr,   g_xr);
    float* p_hid;  cudaGetSymbolAddress((void**)&p_hid,  g_hid);

    dim3 blk(256);
    int rowBlocks = (n + 127) / 128;
    int nBlocks   = (n + 255) / 256;
    int eBlocks   = (E + 255) / 256;
    int scanBlocks = (n + 255) / 256;

    // ---- CSR build (no self loops in CSR; gather adds the self loop) ----
    csr_zero_kernel<<<nBlocks, blk>>>(n);
    csr_count_kernel<<<eBlocks, blk>>>(ei, E);
    scan1_kernel<<<scanBlocks, blk>>>(n);
    scan2_kernel<<<1, blk>>>(scanBlocks);
    scan3_kernel<<<nBlocks, blk>>>(n);
    csr_scatter_kernel<<<eBlocks, blk>>>(ei, E);

    // ---- embedding ----
    tgemm_kernel<<<dim3(rowBlocks, 1, 1), blk>>>(x, emb_W, emb_b, p_h, ACT_RELU,
                                                 nullptr, nullptr, nullptr, 0,
                                                 n, 512, 128, 0);

    int warpGrid = (n * 32 + 255) / 256;

    for (int i = 0; i < 3; i++) {
        ln_kernel<<<warpGrid, blk>>>(p_h, ln1_g + i * D, ln1_b + i * D, p_hn, n);
        // xl = hn@Wl+bl ; xr = hn@Wr+br — one z-batched launch
        tgemm_kernel<<<dim3(rowBlocks, 1, 2), blk>>>(p_hn,
                                                     gat_Wl + i * D * D, gat_bl + i * D, p_xl, ACT_NONE,
                                                     gat_Wr + i * D * D, gat_br + i * D, p_xr, ACT_NONE,
                                                     n, D, D, 0);

        gat_gather_kernel<<<warpGrid, blk>>>(p_xl, p_xr, gat_att + i * D, gat_bias + i * D, n);

        int H = D * (i + 1);
        tgemm_kernel<<<dim3(rowBlocks, H / 128, 1), blk>>>(p_h, w1s[i], nullptr, p_hid, ACT_GELU,
                                                           nullptr, nullptr, nullptr, 0,
                                                           n, D, H, 0);
        tgemm_kernel<<<dim3(rowBlocks, 1, 1), blk>>>(p_hid, w2s[i], nullptr, p_h, ACT_NONE,
                                                     nullptr, nullptr, nullptr, 0,
                                                     n, H, D, 1);
    }

    // ---- pooling: one z-batched launch for ta/tb ----
    tgemm_kernel<<<dim3(rowBlocks, 1, 2), blk>>>(p_h,
                                                 attn_Wa, attn_ba, p_xl, ACT_TANH,
                                                 attn_Wb, attn_bb, p_xr, ACT_SIGM,
                                                 n, D, D, 0);

    init_pool_kernel<<<1, 128>>>();
    pool_score_kernel<<<warpGrid, blk>>>(p_xl, p_xr, attn_Wc, attn_bc, n);
    pool_max_kernel<<<160, blk>>>(n);
    pool_accum_kernel<<<296, blk>>>(n);
    final_kernel<<<1, 128>>>(rho_W, rho_b, cls_W, cls_b, out);

    (void)n_in; (void)out_size;
}

// round 13
// speedup vs baseline: 1.3658x; 1.3658x over previous
#include <cuda_runtime.h>
#include <math.h>
#include <stdint.h>

// ---------------- problem constants ----------------
#define NMAX 50000
#define EMAX 800000
#define D 128
#define HMAX 384

// ---------------- scratch (device globals; no mallocs allowed) ----------------
__device__ float g_h [NMAX * D];
__device__ float g_hn[NMAX * D];
__device__ float g_xl[NMAX * D];
__device__ float g_xr[NMAX * D];
__device__ float g_hid[NMAX * HMAX];
__device__ int   g_cnt[NMAX];
__device__ int   g_row[NMAX];
__device__ int   g_cur[NMAX];
__device__ int   g_csr_src[EMAX];
__device__ int   g_partial[256];
__device__ float g_pool_s[NMAX];
__device__ float g_hp[D];
__device__ float g_sumw;
__device__ unsigned g_maxu;

// ---------------- helpers ----------------
__device__ __forceinline__ unsigned fenc(float f) {
    unsigned b = __float_as_uint(f);
    return (b & 0x80000000u) ? ~b : (b | 0x80000000u);
}
__device__ __forceinline__ float fdec(unsigned u) {
    return __uint_as_float((u & 0x80000000u) ? (u & 0x7FFFFFFFu) : ~u);
}
__device__ __forceinline__ uint32_t f2tf(float f) {
    uint32_t u;
    asm("cvt.rna.tf32.f32 %0, %1;" : "=r"(u) : "f"(f));
    return u;
}

#define ACT_NONE 0
#define ACT_RELU 1
#define ACT_GELU 2
#define ACT_TANH 3
#define ACT_SIGM 4

__device__ __forceinline__ float apply_act(float v, int act) {
    switch (act) {
        case ACT_RELU: return v > 0.f ? v : 0.f;
        case ACT_GELU: return 0.5f * v * (1.f + erff(v * 0.70710678118654752f));
        case ACT_TANH: return tanhf(v);
        case ACT_SIGM: return 1.f / (1.f + expf(-v));
        default: return v;
    }
}

// ---------------- CSR build (round-4 version: NO self loop in CSR) ----------------
__global__ void csr_zero_kernel(int n) {
    int i = blockIdx.x * blockDim.x + threadIdx.x;
    if (i < n) g_cnt[i] = 0;
}
__global__ void csr_count_kernel(const int* __restrict__ ei, int E) {
    int i = blockIdx.x * blockDim.x + threadIdx.x;
    if (i < E) atomicAdd(&g_cnt[ei[E + i]], 1);
}
__global__ void scan1_kernel(int n) {
    __shared__ int sm[256];
    int t = threadIdx.x;
    int i = blockIdx.x * 256 + t;
    int v = (i < n) ? g_cnt[i] : 0;
    sm[t] = v;
    __syncthreads();
#pragma unroll
    for (int off = 1; off < 256; off <<= 1) {
        int a = (t >= off) ? sm[t - off] : 0;
        __syncthreads();
        sm[t] += a;
        __syncthreads();
    }
    if (i < n) g_row[i] = sm[t] - v;   // exclusive
    if (t == 255) g_partial[blockIdx.x] = sm[255];
}
__global__ void scan2_kernel(int nb) {
    __shared__ int sm[256];
    int t = threadIdx.x;
    int v = (t < nb) ? g_partial[t] : 0;
    sm[t] = v;
    __syncthreads();
#pragma unroll
    for (int off = 1; off < 256; off <<= 1) {
        int a = (t >= off) ? sm[t - off] : 0;
        __syncthreads();
        sm[t] += a;
        __syncthreads();
    }
    if (t < nb) g_partial[t] = sm[t] - v;  // exclusive
}
__global__ void scan3_kernel(int n) {
    int i = blockIdx.x * blockDim.x + threadIdx.x;
    if (i < n) {
        int v = g_row[i] + g_partial[i >> 8];
        g_row[i] = v;
        g_cur[i] = v;
    }
}
__global__ void csr_scatter_kernel(const int* __restrict__ ei, int E) {
    int i = blockIdx.x * blockDim.x + threadIdx.x;
    if (i < E) {
        int d = ei[E + i];
        int slot = atomicAdd(&g_cur[d], 1);
        g_csr_src[slot] = ei[i];
    }
}

// ---------------- init ----------------
__global__ void init_pool_kernel() {
    int t = threadIdx.x;
    g_hp[t] = 0.f;
    if (t == 0) { g_sumw = 0.f; g_maxu = 0u; }
}

// ---------------- tf32 tensor-core GEMM (round-2/4 proven version, NO z-batch) ----------------
__global__ __launch_bounds__(256, 2)
void tgemm_kernel(const float* __restrict__ A, const float* __restrict__ B,
                  const float* __restrict__ bias, float* __restrict__ C,
                  int n, int K, int M, int act, int residual)
{
    __shared__ uint32_t sA[128][36];
    __shared__ uint32_t sB[32][136];

    int tid  = threadIdx.x;
    int lane = tid & 31;
    int warp = tid >> 5;
    int g    = lane >> 2;
    int tig  = lane & 3;
    int mW   = (warp & 3) * 32;
    int nW   = (warp >> 2) * 64;
    int rowBase = blockIdx.x * 128;
    int colBase = blockIdx.y * 128;

    float acc[2][8][4];
#pragma unroll
    for (int mt = 0; mt < 2; mt++)
#pragma unroll
        for (int nt = 0; nt < 8; nt++)
#pragma unroll
            for (int c = 0; c < 4; c++) acc[mt][nt][c] = 0.f;

    for (int k0 = 0; k0 < K; k0 += 32) {
#pragma unroll
        for (int i = 0; i < 4; i++) {
            int idx = tid + 256 * i;
            int r   = idx >> 3;
            int kc  = (idx & 7) * 4;
            int gr  = rowBase + r;
            float4 v = make_float4(0.f, 0.f, 0.f, 0.f);
            if (gr < n) v = *reinterpret_cast<const float4*>(A + (size_t)gr * K + k0 + kc);
            sA[r][kc + 0] = f2tf(v.x);
            sA[r][kc + 1] = f2tf(v.y);
            sA[r][kc + 2] = f2tf(v.z);
            sA[r][kc + 3] = f2tf(v.w);
        }
#pragma unroll
        for (int i = 0; i < 4; i++) {
            int idx = tid + 256 * i;
            int kr  = idx >> 5;
            int c   = (idx & 31) * 4;
            float4 v = *reinterpret_cast<const float4*>(B + (size_t)(k0 + kr) * M + colBase + c);
            sB[kr][c + 0] = f2tf(v.x);
            sB[kr][c + 1] = f2tf(v.y);
            sB[kr][c + 2] = f2tf(v.z);
            sB[kr][c + 3] = f2tf(v.w);
        }
        __syncthreads();

#pragma unroll
        for (int kt = 0; kt < 4; kt++) {
            int kb = kt * 8;
            uint32_t a[2][4], b[8][2];
#pragma unroll
            for (int mt = 0; mt < 2; mt++) {
                int mb = mW + mt * 16;
                a[mt][0] = sA[mb + g    ][kb + tig    ];
                a[mt][1] = sA[mb + g + 8][kb + tig    ];
                a[mt][2] = sA[mb + g    ][kb + tig + 4];
                a[mt][3] = sA[mb + g + 8][kb + tig + 4];
            }
#pragma unroll
            for (int nt = 0; nt < 8; nt++) {
                int nb = nW + nt * 8;
                b[nt][0] = sB[kb + tig    ][nb + g];
                b[nt][1] = sB[kb + tig + 4][nb + g];
            }
#pragma unroll
            for (int mt = 0; mt < 2; mt++)
#pragma unroll
                for (int nt = 0; nt < 8; nt++) {
                    asm volatile(
                        "mma.sync.aligned.m16n8k8.row.col.f32.tf32.tf32.f32 "
                        "{%0,%1,%2,%3}, {%4,%5,%6,%7}, {%8,%9}, {%0,%1,%2,%3};"
                        : "+f"(acc[mt][nt][0]), "+f"(acc[mt][nt][1]),
                          "+f"(acc[mt][nt][2]), "+f"(acc[mt][nt][3])
                        : "r"(a[mt][0]), "r"(a[mt][1]), "r"(a[mt][2]), "r"(a[mt][3]),
                          "r"(b[nt][0]), "r"(b[nt][1]));
                }
        }
        __syncthreads();
    }

#pragma unroll
    for (int mt = 0; mt < 2; mt++) {
#pragma unroll
        for (int half = 0; half < 2; half++) {
            int gr = rowBase + mW + mt * 16 + g + half * 8;
            if (gr >= n) continue;
#pragma unroll
            for (int nt = 0; nt < 8; nt++) {
#pragma unroll
                for (int j = 0; j < 2; j++) {
                    int gc = colBase + nW + nt * 8 + tig * 2 + j;
                    float v = acc[mt][nt][half * 2 + j];
                    if (bias) v += bias[gc];
                    v = apply_act(v, act);
                    size_t o = (size_t)gr * M + gc;
                    if (residual) C[o] = C[o] + v; else C[o] = v;
                }
            }
        }
    }
}

// ---------------- LayerNorm (warp per row, float4) ----------------
__global__ void ln_kernel(const float* __restrict__ X, const float* __restrict__ g,
                          const float* __restrict__ b, float* __restrict__ Y, int n)
{
    int w = (blockIdx.x * blockDim.x + threadIdx.x) >> 5;
    int lane = threadIdx.x & 31;
    if (w >= n) return;
    float4 v = reinterpret_cast<const float4*>(X + (size_t)w * D)[lane];
    float s  = v.x + v.y + v.z + v.w;
    float s2 = v.x * v.x + v.y * v.y + v.z * v.z + v.w * v.w;
#pragma unroll
    for (int off = 16; off > 0; off >>= 1) {
        s  += __shfl_xor_sync(0xFFFFFFFFu, s,  off);
        s2 += __shfl_xor_sync(0xFFFFFFFFu, s2, off);
    }
    float mu = s * (1.f / 128.f);
    float var = s2 * (1.f / 128.f) - mu * mu;
    float rstd = rsqrtf(var + 1e-5f);
    float4 gg = reinterpret_cast<const float4*>(g)[lane];
    float4 bb = reinterpret_cast<const float4*>(b)[lane];
    float4 o;
    o.x = (v.x - mu) * rstd * gg.x + bb.x;
    o.y = (v.y - mu) * rstd * gg.y + bb.y;
    o.z = (v.z - mu) * rstd * gg.z + bb.z;
    o.w = (v.w - mu) * rstd * gg.w + bb.w;
    reinterpret_cast<float4*>(Y + (size_t)w * D)[lane] = o;
}

// ---------------- GATv2: TWO warps per node, R4 loop body, smem merge ----------------
// Warp half 0: self loop + edges [beg, beg+cnt/2). Warp half 1: edges [beg+cnt/2, beg+cnt).
// Loop body identical to the proven round-4 kernel (full-warp reductions, warp-uniform rescale).
__global__ __launch_bounds__(256)
void gat_gather_kernel(const float* __restrict__ xl, const float* __restrict__ xr,
                       const float* __restrict__ att, const float* __restrict__ bias,
                       int n)
{
    __shared__ float  s_m[4];
    __shared__ float  s_den[4];
    __shared__ float4 s_acc[4][32];

    int gwarp = (blockIdx.x * blockDim.x + threadIdx.x) >> 5;
    int node  = gwarp >> 1;
    int half  = gwarp & 1;
    int lane  = threadIdx.x & 31;
    int pair  = (threadIdx.x >> 6);      // 0..3 : node slot within block
    bool valid = (node < n);

    float m = -1e30f, den = 0.f;
    float4 acc = make_float4(0.f, 0.f, 0.f, 0.f);
    float4 at4, xr4;

    int beg = 0, lo = 0, hi = 0;
    if (valid) {
        at4 = reinterpret_cast<const float4*>(att)[lane];
        xr4 = reinterpret_cast<const float4*>(xr + (size_t)node * D)[lane];
        beg = g_row[node];
        int cnt = g_cnt[node];
        int h0 = cnt >> 1;
        lo = (half == 0) ? 0 : h0;
        hi = (half == 0) ? h0 : cnt;

        if (half == 0) {
            // self loop first (exactly as round 4)
            float4 v4 = reinterpret_cast<const float4*>(xl + (size_t)node * D)[lane];
            float ex = v4.x + xr4.x; ex = ex > 0.f ? ex : 0.2f * ex;
            float ey = v4.y + xr4.y; ey = ey > 0.f ? ey : 0.2f * ey;
            float ez = v4.z + xr4.z; ez = ez > 0.f ? ez : 0.2f * ez;
            float ew = v4.w + xr4.w; ew = ew > 0.f ? ew : 0.2f * ew;
            float sc = ex * at4.x + ey * at4.y + ez * at4.z + ew * at4.w;
#pragma unroll
            for (int off = 16; off > 0; off >>= 1) sc += __shfl_xor_sync(0xFFFFFFFFu, sc, off);
            m = sc; den = 1.f; acc = v4;
        }

        for (int j = beg + lo; j < beg + hi; j++) {
            int s = g_csr_src[j];
            float4 v4 = reinterpret_cast<const float4*>(xl + (size_t)s * D)[lane];
            float ex = v4.x + xr4.x; ex = ex > 0.f ? ex : 0.2f * ex;
            float ey = v4.y + xr4.y; ey = ey > 0.f ? ey : 0.2f * ey;
            float ez = v4.z + xr4.z; ez = ez > 0.f ? ez : 0.2f * ez;
            float ew = v4.w + xr4.w; ew = ew > 0.f ? ew : 0.2f * ew;
            float sc = ex * at4.x + ey * at4.y + ez * at4.z + ew * at4.w;
#pragma unroll
            for (int off = 16; off > 0; off >>= 1) sc += __shfl_xor_sync(0xFFFFFFFFu, sc, off);
            if (sc > m) {
                float f = expf(m - sc);
                den *= f;
                acc.x *= f; acc.y *= f; acc.z *= f; acc.w *= f;
                m = sc;
            }
            float w = expf(sc - m);
            den += w;
            acc.x += w * v4.x; acc.y += w * v4.y; acc.z += w * v4.z; acc.w += w * v4.w;
        }
    }

    // merge: half-1 warp publishes its state, half-0 warp combines and writes out
    if (valid && half == 1) {
        if (lane == 0) { s_m[pair] = m; s_den[pair] = den; }
        s_acc[pair][lane] = acc;
    }
    __syncthreads();
    if (valid && half == 0) {
        float  mB   = s_m[pair];
        float  denB = s_den[pair];
        float4 accB = s_acc[pair][lane];
        float mAll = fmaxf(m, mB);
        float fA = expf(m - mAll);
        float fB = expf(mB - mAll);     // 0 when half-1 range was empty
        den = den * fA + denB * fB;
        acc.x = acc.x * fA + accB.x * fB;
        acc.y = acc.y * fA + accB.y * fB;
        acc.z = acc.z * fA + accB.z * fB;
        acc.w = acc.w * fA + accB.w * fB;

        float inv = 1.f / den;
        float4 bb = reinterpret_cast<const float4*>(bias)[lane];
        float4* hp = reinterpret_cast<float4*>(g_h + (size_t)node * D);
        float4 h = hp[lane];
        h.x += acc.x * inv + bb.x;
        h.y += acc.y * inv + bb.y;
        h.z += acc.z * inv + bb.z;
        h.w += acc.w * inv + bb.w;
        hp[lane] = h;
    }
}

// ---------------- pooling ----------------
__global__ void pool_score_kernel(const float* __restrict__ ta, const float* __restrict__ tb,
                                  const float* __restrict__ Wc, const float* __restrict__ bc, int n)
{
    int w = (blockIdx.x * blockDim.x + threadIdx.x) >> 5;
    int lane = threadIdx.x & 31;
    if (w >= n) return;
    float4 a = reinterpret_cast<const float4*>(ta + (size_t)w * D)[lane];
    float4 b = reinterpret_cast<const float4*>(tb + (size_t)w * D)[lane];
    float4 c = reinterpret_cast<const float4*>(Wc)[lane];
    float acc = a.x * b.x * c.x + a.y * b.y * c.y + a.z * b.z * c.z + a.w * b.w * c.w;
#pragma unroll
    for (int off = 16; off > 0; off >>= 1) acc += __shfl_xor_sync(0xFFFFFFFFu, acc, off);
    if (lane == 0) g_pool_s[w] = acc + bc[0];
}

__global__ void pool_max_kernel(int n)
{
    __shared__ float sm[256];
    int t = threadIdx.x;
    float m = -1e30f;
    for (int i = blockIdx.x * blockDim.x + t; i < n; i += gridDim.x * blockDim.x)
        m = fmaxf(m, g_pool_s[i]);
    sm[t] = m;
    __syncthreads();
    for (int s = 128; s > 0; s >>= 1) {
        if (t < s) sm[t] = fmaxf(sm[t], sm[t + s]);
        __syncthreads();
    }
    if (t == 0) atomicMax(&g_maxu, fenc(sm[0]));
}

__global__ void pool_accum_kernel(int n)
{
    __shared__ float sacc[D];
    int t = threadIdx.x;
    int lane = t & 31;
    if (t < D) sacc[t] = 0.f;
    __syncthreads();
    float mx = fdec(g_maxu);
    float4 racc = make_float4(0.f, 0.f, 0.f, 0.f);
    float wsum = 0.f;
    int nwarps = (gridDim.x * blockDim.x) >> 5;
    for (int nd = (blockIdx.x * blockDim.x + t) >> 5; nd < n; nd += nwarps) {
        float w = expf(g_pool_s[nd] - mx);
        if (lane == 0) wsum += w;
        float4 v = reinterpret_cast<const float4*>(g_h + (size_t)nd * D)[lane];
        racc.x += w * v.x; racc.y += w * v.y; racc.z += w * v.z; racc.w += w * v.w;
    }
    atomicAdd(&sacc[lane * 4 + 0], racc.x);
    atomicAdd(&sacc[lane * 4 + 1], racc.y);
    atomicAdd(&sacc[lane * 4 + 2], racc.z);
    atomicAdd(&sacc[lane * 4 + 3], racc.w);
    __syncthreads();
    if (t < D) atomicAdd(&g_hp[t], sacc[t]);
    if (lane == 0 && wsum != 0.f) atomicAdd(&g_sumw, wsum);
}

// ---------------- final head ----------------
__global__ void final_kernel(const float* __restrict__ rho_W, const float* __restrict__ rho_b,
                             const float* __restrict__ cls_W, const float* __restrict__ cls_b,
                             float* __restrict__ out)
{
    __shared__ float hp[D];
    __shared__ float hr[D];
    __shared__ float slog[4];
    int t = threadIdx.x;
    hp[t] = g_hp[t] / g_sumw;
    __syncthreads();
    float a = rho_b[t];
#pragma unroll 4
    for (int k = 0; k < D; k++) a += hp[k] * rho_W[k * D + t];
    hr[t] = a > 0.f ? a : 0.f;
    __syncthreads();
    if (t < 4) {
        float lg = cls_b[t];
#pragma unroll 4
        for (int d = 0; d < D; d++) lg += hr[d] * cls_W[d * 4 + t];
        slog[t] = lg;
    }
    __syncthreads();
    if (t == 0) {
        float hz[4], S[4];
        int am = 0;
        float best = slog[0];
        for (int c = 0; c < 4; c++) {
            hz[c] = 1.f / (1.f + expf(-slog[c]));
            if (slog[c] > best) { best = slog[c]; am = c; }
        }
        S[0] = 1.f - hz[0];
        for (int c = 1; c < 4; c++) S[c] = S[c - 1] * (1.f - hz[c]);
        for (int c = 0; c < 4; c++) out[c] = hz[c];
        for (int c = 0; c < 4; c++) out[4 + c] = S[c];
        out[8] = (float)am;
        for (int c = 0; c < 4; c++) out[9 + c] = slog[c];
    }
}

// ---------------- launch ----------------
extern "C" void kernel_launch(void* const* d_in, const int* in_sizes, int n_in,
                              void* d_out, int out_size)
{
    const float* x      = (const float*)d_in[0];
    const int*   ei     = (const int*)d_in[1];
    const float* emb_W  = (const float*)d_in[2];
    const float* emb_b  = (const float*)d_in[3];
    const float* ln1_g  = (const float*)d_in[4];
    const float* ln1_b  = (const float*)d_in[5];
    const float* gat_Wl = (const float*)d_in[6];
    const float* gat_bl = (const float*)d_in[7];
    const float* gat_Wr = (const float*)d_in[8];
    const float* gat_br = (const float*)d_in[9];
    const float* gat_att  = (const float*)d_in[10];
    const float* gat_bias = (const float*)d_in[11];
    const float* w1s[3] = {(const float*)d_in[12], (const float*)d_in[14], (const float*)d_in[16]};
    const float* w2s[3] = {(const float*)d_in[13], (const float*)d_in[15], (const float*)d_in[17]};
    const float* attn_Wa = (const float*)d_in[18];
    const float* attn_ba = (const float*)d_in[19];
    const float* attn_Wb = (const float*)d_in[20];
    const float* attn_bb = (const float*)d_in[21];
    const float* attn_Wc = (const float*)d_in[22];
    const float* attn_bc = (const float*)d_in[23];
    const float* rho_W   = (const float*)d_in[24];
    const float* rho_b   = (const float*)d_in[25];
    const float* cls_W   = (const float*)d_in[26];
    const float* cls_b   = (const float*)d_in[27];
    float* out = (float*)d_out;

    int n  = in_sizes[0] / 512;     // 50000
    int E  = in_sizes[1] / 2;       // 800000

    float* p_h;    cudaGetSymbolAddress((void**)&p_h,    g_h);
    float* p_hn;   cudaGetSymbolAddress((void**)&p_hn,   g_hn);
    float* p_xl;   cudaGetSymbolAddress((void**)&p_xl,   g_xl);
    float* p_xr;   cudaGetSymbolAddress((void**)&p_xr,   g_xr);
    float* p_hid;  cudaGetSymbolAddress((void**)&p_hid,  g_hid);

    dim3 blk(256);
    int rowBlocks = (n + 127) / 128;
    int nBlocks   = (n + 255) / 256;
    int eBlocks   = (E + 255) / 256;
    int scanBlocks = (n + 255) / 256;

    // ---- CSR build ----
    csr_zero_kernel<<<nBlocks, blk>>>(n);
    csr_count_kernel<<<eBlocks, blk>>>(ei, E);
    scan1_kernel<<<scanBlocks, blk>>>(n);
    scan2_kernel<<<1, blk>>>(scanBlocks);
    scan3_kernel<<<nBlocks, blk>>>(n);
    csr_scatter_kernel<<<eBlocks, blk>>>(ei, E);

    // ---- embedding ----
    tgemm_kernel<<<dim3(rowBlocks, 1), blk>>>(x, emb_W, emb_b, p_h, n, 512, 128, ACT_RELU, 0);

    int warpGrid  = (n * 32 + 255) / 256;
    int gatherGrid = (n * 64 + 255) / 256;   // 2 warps per node

    for (int i = 0; i < 3; i++) {
        ln_kernel<<<warpGrid, blk>>>(p_h, ln1_g + i * D, ln1_b + i * D, p_hn, n);
        tgemm_kernel<<<dim3(rowBlocks, 1), blk>>>(p_hn, gat_Wl + i * D * D, gat_bl + i * D, p_xl, n, D, D, ACT_NONE, 0);
        tgemm_kernel<<<dim3(rowBlocks, 1), blk>>>(p_hn, gat_Wr + i * D * D, gat_br + i * D, p_xr, n, D, D, ACT_NONE, 0);

        gat_gather_kernel<<<gatherGrid, blk>>>(p_xl, p_xr, gat_att + i * D, gat_bias + i * D, n);

        int H = D * (i + 1);
        tgemm_kernel<<<dim3(rowBlocks, H / 128), blk>>>(p_h, w1s[i], nullptr, p_hid, n, D, H, ACT_GELU, 0);
        tgemm_kernel<<<dim3(rowBlocks, 1), blk>>>(p_hid, w2s[i], nullptr, p_h, n, H, D, ACT_NONE, 1);
    }

    // ---- pooling ----
    tgemm_kernel<<<dim3(rowBlocks, 1), blk>>>(p_h, attn_Wa, attn_ba, p_xl, n, D, D, ACT_TANH, 0);
    tgemm_kernel<<<dim3(rowBlocks, 1), blk>>>(p_h, attn_Wb, attn_bb, p_xr, n, D, D, ACT_SIGM, 0);

    init_pool_kernel<<<1, 128>>>();
    pool_score_kernel<<<warpGrid, blk>>>(p_xl, p_xr, attn_Wc, attn_bc, n);
    pool_max_kernel<<<160, blk>>>(n);
    pool_accum_kernel<<<296, blk>>>(n);
    final_kernel<<<1, 128>>>(rho_W, rho_b, cls_W, cls_b, out);

    (void)n_in; (void)out_size;
}

// round 14
// speedup vs baseline: 1.3870x; 1.0156x over previous
#include <cuda_runtime.h>
#include <cuda_fp16.h>
#include <math.h>
#include <stdint.h>

// ---------------- problem constants ----------------
#define NMAX 50000
#define EMAX 800000
#define D 128
#define HMAX 384

// ---------------- scratch (device globals; no mallocs allowed) ----------------
__device__ float  g_h [NMAX * D];
__device__ float  g_hn[NMAX * D];
__device__ __half g_xl[NMAX * D];       // fp16: halves gather traffic
__device__ float  g_xr[NMAX * D];
__device__ float  g_hid[NMAX * HMAX];
__device__ int    g_cnt[NMAX];
__device__ int    g_row[NMAX];
__device__ int    g_cur[NMAX];
__device__ int    g_csr_src[EMAX];
__device__ int    g_partial[256];
__device__ float  g_pool_s[NMAX];
__device__ float  g_hp[D];
__device__ float  g_sumw;
__device__ unsigned g_maxu;

// ---------------- helpers ----------------
__device__ __forceinline__ unsigned fenc(float f) {
    unsigned b = __float_as_uint(f);
    return (b & 0x80000000u) ? ~b : (b | 0x80000000u);
}
__device__ __forceinline__ float fdec(unsigned u) {
    return __uint_as_float((u & 0x80000000u) ? (u & 0x7FFFFFFFu) : ~u);
}
__device__ __forceinline__ uint32_t f2tf(float f) {
    uint32_t u;
    asm("cvt.rna.tf32.f32 %0, %1;" : "=r"(u) : "f"(f));
    return u;
}

#define ACT_NONE 0
#define ACT_RELU 1
#define ACT_GELU 2
#define ACT_TANH 3
#define ACT_SIGM 4

__device__ __forceinline__ float apply_act(float v, int act) {
    switch (act) {
        case ACT_RELU: return v > 0.f ? v : 0.f;
        case ACT_GELU: return 0.5f * v * (1.f + erff(v * 0.70710678118654752f));
        case ACT_TANH: return tanhf(v);
        case ACT_SIGM: return 1.f / (1.f + expf(-v));
        default: return v;
    }
}

// ---------------- CSR build (round-4 version: NO self loop in CSR) ----------------
__global__ void csr_zero_kernel(int n) {
    int i = blockIdx.x * blockDim.x + threadIdx.x;
    if (i < n) g_cnt[i] = 0;
}
__global__ void csr_count_kernel(const int* __restrict__ ei, int E) {
    int i = blockIdx.x * blockDim.x + threadIdx.x;
    if (i < E) atomicAdd(&g_cnt[ei[E + i]], 1);
}
__global__ void scan1_kernel(int n) {
    __shared__ int sm[256];
    int t = threadIdx.x;
    int i = blockIdx.x * 256 + t;
    int v = (i < n) ? g_cnt[i] : 0;
    sm[t] = v;
    __syncthreads();
#pragma unroll
    for (int off = 1; off < 256; off <<= 1) {
        int a = (t >= off) ? sm[t - off] : 0;
        __syncthreads();
        sm[t] += a;
        __syncthreads();
    }
    if (i < n) g_row[i] = sm[t] - v;   // exclusive
    if (t == 255) g_partial[blockIdx.x] = sm[255];
}
__global__ void scan2_kernel(int nb) {
    __shared__ int sm[256];
    int t = threadIdx.x;
    int v = (t < nb) ? g_partial[t] : 0;
    sm[t] = v;
    __syncthreads();
#pragma unroll
    for (int off = 1; off < 256; off <<= 1) {
        int a = (t >= off) ? sm[t - off] : 0;
        __syncthreads();
        sm[t] += a;
        __syncthreads();
    }
    if (t < nb) g_partial[t] = sm[t] - v;  // exclusive
}
__global__ void scan3_kernel(int n) {
    int i = blockIdx.x * blockDim.x + threadIdx.x;
    if (i < n) {
        int v = g_row[i] + g_partial[i >> 8];
        g_row[i] = v;
        g_cur[i] = v;
    }
}
__global__ void csr_scatter_kernel(const int* __restrict__ ei, int E) {
    int i = blockIdx.x * blockDim.x + threadIdx.x;
    if (i < E) {
        int d = ei[E + i];
        int slot = atomicAdd(&g_cur[d], 1);
        g_csr_src[slot] = ei[i];
    }
}

// ---------------- init ----------------
__global__ void init_pool_kernel() {
    int t = threadIdx.x;
    g_hp[t] = 0.f;
    if (t == 0) { g_sumw = 0.f; g_maxu = 0u; }
}

// ---------------- tf32 tensor-core GEMM (round-4 proven; optional fp16 output) ----------------
__global__ __launch_bounds__(256, 2)
void tgemm_kernel(const float* __restrict__ A, const float* __restrict__ B,
                  const float* __restrict__ bias, float* __restrict__ C,
                  int n, int K, int M, int act, int residual, int outHalf)
{
    __shared__ uint32_t sA[128][36];
    __shared__ uint32_t sB[32][136];

    int tid  = threadIdx.x;
    int lane = tid & 31;
    int warp = tid >> 5;
    int g    = lane >> 2;
    int tig  = lane & 3;
    int mW   = (warp & 3) * 32;
    int nW   = (warp >> 2) * 64;
    int rowBase = blockIdx.x * 128;
    int colBase = blockIdx.y * 128;

    float acc[2][8][4];
#pragma unroll
    for (int mt = 0; mt < 2; mt++)
#pragma unroll
        for (int nt = 0; nt < 8; nt++)
#pragma unroll
            for (int c = 0; c < 4; c++) acc[mt][nt][c] = 0.f;

    for (int k0 = 0; k0 < K; k0 += 32) {
#pragma unroll
        for (int i = 0; i < 4; i++) {
            int idx = tid + 256 * i;
            int r   = idx >> 3;
            int kc  = (idx & 7) * 4;
            int gr  = rowBase + r;
            float4 v = make_float4(0.f, 0.f, 0.f, 0.f);
            if (gr < n) v = *reinterpret_cast<const float4*>(A + (size_t)gr * K + k0 + kc);
            sA[r][kc + 0] = f2tf(v.x);
            sA[r][kc + 1] = f2tf(v.y);
            sA[r][kc + 2] = f2tf(v.z);
            sA[r][kc + 3] = f2tf(v.w);
        }
#pragma unroll
        for (int i = 0; i < 4; i++) {
            int idx = tid + 256 * i;
            int kr  = idx >> 5;
            int c   = (idx & 31) * 4;
            float4 v = *reinterpret_cast<const float4*>(B + (size_t)(k0 + kr) * M + colBase + c);
            sB[kr][c + 0] = f2tf(v.x);
            sB[kr][c + 1] = f2tf(v.y);
            sB[kr][c + 2] = f2tf(v.z);
            sB[kr][c + 3] = f2tf(v.w);
        }
        __syncthreads();

#pragma unroll
        for (int kt = 0; kt < 4; kt++) {
            int kb = kt * 8;
            uint32_t a[2][4], b[8][2];
#pragma unroll
            for (int mt = 0; mt < 2; mt++) {
                int mb = mW + mt * 16;
                a[mt][0] = sA[mb + g    ][kb + tig    ];
                a[mt][1] = sA[mb + g + 8][kb + tig    ];
                a[mt][2] = sA[mb + g    ][kb + tig + 4];
                a[mt][3] = sA[mb + g + 8][kb + tig + 4];
            }
#pragma unroll
            for (int nt = 0; nt < 8; nt++) {
                int nb = nW + nt * 8;
                b[nt][0] = sB[kb + tig    ][nb + g];
                b[nt][1] = sB[kb + tig + 4][nb + g];
            }
#pragma unroll
            for (int mt = 0; mt < 2; mt++)
#pragma unroll
                for (int nt = 0; nt < 8; nt++) {
                    asm volatile(
                        "mma.sync.aligned.m16n8k8.row.col.f32.tf32.tf32.f32 "
                        "{%0,%1,%2,%3}, {%4,%5,%6,%7}, {%8,%9}, {%0,%1,%2,%3};"
                        : "+f"(acc[mt][nt][0]), "+f"(acc[mt][nt][1]),
                          "+f"(acc[mt][nt][2]), "+f"(acc[mt][nt][3])
                        : "r"(a[mt][0]), "r"(a[mt][1]), "r"(a[mt][2]), "r"(a[mt][3]),
                          "r"(b[nt][0]), "r"(b[nt][1]));
                }
        }
        __syncthreads();
    }

#pragma unroll
    for (int mt = 0; mt < 2; mt++) {
#pragma unroll
        for (int half = 0; half < 2; half++) {
            int gr = rowBase + mW + mt * 16 + g + half * 8;
            if (gr >= n) continue;
#pragma unroll
            for (int nt = 0; nt < 8; nt++) {
#pragma unroll
                for (int j = 0; j < 2; j++) {
                    int gc = colBase + nW + nt * 8 + tig * 2 + j;
                    float v = acc[mt][nt][half * 2 + j];
                    if (bias) v += bias[gc];
                    v = apply_act(v, act);
                    size_t o = (size_t)gr * M + gc;
                    if (outHalf) {
                        reinterpret_cast<__half*>(C)[o] = __float2half_rn(v);
                    } else if (residual) {
                        C[o] = C[o] + v;
                    } else {
                        C[o] = v;
                    }
                }
            }
        }
    }
}

// ---------------- LayerNorm (warp per row, float4) ----------------
__global__ void ln_kernel(const float* __restrict__ X, const float* __restrict__ g,
                          const float* __restrict__ b, float* __restrict__ Y, int n)
{
    int w = (blockIdx.x * blockDim.x + threadIdx.x) >> 5;
    int lane = threadIdx.x & 31;
    if (w >= n) return;
    float4 v = reinterpret_cast<const float4*>(X + (size_t)w * D)[lane];
    float s  = v.x + v.y + v.z + v.w;
    float s2 = v.x * v.x + v.y * v.y + v.z * v.z + v.w * v.w;
#pragma unroll
    for (int off = 16; off > 0; off >>= 1) {
        s  += __shfl_xor_sync(0xFFFFFFFFu, s,  off);
        s2 += __shfl_xor_sync(0xFFFFFFFFu, s2, off);
    }
    float mu = s * (1.f / 128.f);
    float var = s2 * (1.f / 128.f) - mu * mu;
    float rstd = rsqrtf(var + 1e-5f);
    float4 gg = reinterpret_cast<const float4*>(g)[lane];
    float4 bb = reinterpret_cast<const float4*>(b)[lane];
    float4 o;
    o.x = (v.x - mu) * rstd * gg.x + bb.x;
    o.y = (v.y - mu) * rstd * gg.y + bb.y;
    o.z = (v.z - mu) * rstd * gg.z + bb.z;
    o.w = (v.w - mu) * rstd * gg.w + bb.w;
    reinterpret_cast<float4*>(Y + (size_t)w * D)[lane] = o;
}

// ---------------- GATv2 fused: warp per node, online softmax (R4 body, xl in fp16) ----------------
__device__ __forceinline__ float4 load_half_row(const __half* row, int lane) {
    uint2 u = reinterpret_cast<const uint2*>(row)[lane];   // 4 halves, 8B/lane, 256B/row
    __half2 h01 = *reinterpret_cast<__half2*>(&u.x);
    __half2 h23 = *reinterpret_cast<__half2*>(&u.y);
    float2 f01 = __half22float2(h01);
    float2 f23 = __half22float2(h23);
    return make_float4(f01.x, f01.y, f23.x, f23.y);
}

__global__ void gat_gather_kernel(const __half* __restrict__ xl, const float* __restrict__ xr,
                                  const float* __restrict__ att, const float* __restrict__ bias,
                                  int n)
{
    int node = (blockIdx.x * blockDim.x + threadIdx.x) >> 5;
    int lane = threadIdx.x & 31;
    if (node >= n) return;

    float4 at4 = reinterpret_cast<const float4*>(att)[lane];
    float4 xr4 = reinterpret_cast<const float4*>(xr + (size_t)node * D)[lane];

    // self loop first (appended self loops in reference)
    float4 v4 = load_half_row(xl + (size_t)node * D, lane);
    float ex, ey, ez, ew, sc;
    {
        ex = v4.x + xr4.x; ex = ex > 0.f ? ex : 0.2f * ex;
        ey = v4.y + xr4.y; ey = ey > 0.f ? ey : 0.2f * ey;
        ez = v4.z + xr4.z; ez = ez > 0.f ? ez : 0.2f * ez;
        ew = v4.w + xr4.w; ew = ew > 0.f ? ew : 0.2f * ew;
        sc = ex * at4.x + ey * at4.y + ez * at4.z + ew * at4.w;
#pragma unroll
        for (int off = 16; off > 0; off >>= 1) sc += __shfl_xor_sync(0xFFFFFFFFu, sc, off);
    }
    float m = sc;
    float den = 1.f;
    float4 acc = v4;   // weight exp(sc - m) = 1

    int beg = g_row[node];
    int end = beg + g_cnt[node];
    for (int j = beg; j < end; j++) {
        int s = g_csr_src[j];
        v4 = load_half_row(xl + (size_t)s * D, lane);
        ex = v4.x + xr4.x; ex = ex > 0.f ? ex : 0.2f * ex;
        ey = v4.y + xr4.y; ey = ey > 0.f ? ey : 0.2f * ey;
        ez = v4.z + xr4.z; ez = ez > 0.f ? ez : 0.2f * ez;
        ew = v4.w + xr4.w; ew = ew > 0.f ? ew : 0.2f * ew;
        sc = ex * at4.x + ey * at4.y + ez * at4.z + ew * at4.w;
#pragma unroll
        for (int off = 16; off > 0; off >>= 1) sc += __shfl_xor_sync(0xFFFFFFFFu, sc, off);
        if (sc > m) {
            float f = expf(m - sc);
            den *= f;
            acc.x *= f; acc.y *= f; acc.z *= f; acc.w *= f;
            m = sc;
        }
        float w = expf(sc - m);
        den += w;
        acc.x += w * v4.x; acc.y += w * v4.y; acc.z += w * v4.z; acc.w += w * v4.w;
    }

    float inv = 1.f / den;
    float4 bb = reinterpret_cast<const float4*>(bias)[lane];
    float4* hp = reinterpret_cast<float4*>(g_h + (size_t)node * D);
    float4 h = hp[lane];
    h.x += acc.x * inv + bb.x;
    h.y += acc.y * inv + bb.y;
    h.z += acc.z * inv + bb.z;
    h.w += acc.w * inv + bb.w;
    hp[lane] = h;
}

// ---------------- pooling ----------------
__global__ void pool_score_kernel(const float* __restrict__ ta, const float* __restrict__ tb,
                                  const float* __restrict__ Wc, const float* __restrict__ bc, int n)
{
    int w = (blockIdx.x * blockDim.x + threadIdx.x) >> 5;
    int lane = threadIdx.x & 31;
    if (w >= n) return;
    float4 a = reinterpret_cast<const float4*>(ta + (size_t)w * D)[lane];
    float4 b = reinterpret_cast<const float4*>(tb + (size_t)w * D)[lane];
    float4 c = reinterpret_cast<const float4*>(Wc)[lane];
    float acc = a.x * b.x * c.x + a.y * b.y * c.y + a.z * b.z * c.z + a.w * b.w * c.w;
#pragma unroll
    for (int off = 16; off > 0; off >>= 1) acc += __shfl_xor_sync(0xFFFFFFFFu, acc, off);
    if (lane == 0) g_pool_s[w] = acc + bc[0];
}

__global__ void pool_max_kernel(int n)
{
    __shared__ float sm[256];
    int t = threadIdx.x;
    float m = -1e30f;
    for (int i = blockIdx.x * blockDim.x + t; i < n; i += gridDim.x * blockDim.x)
        m = fmaxf(m, g_pool_s[i]);
    sm[t] = m;
    __syncthreads();
    for (int s = 128; s > 0; s >>= 1) {
        if (t < s) sm[t] = fmaxf(sm[t], sm[t + s]);
        __syncthreads();
    }
    if (t == 0) atomicMax(&g_maxu, fenc(sm[0]));
}

__global__ void pool_accum_kernel(int n)
{
    __shared__ float sacc[D];
    int t = threadIdx.x;
    int lane = t & 31;
    if (t < D) sacc[t] = 0.f;
    __syncthreads();
    float mx = fdec(g_maxu);
    float4 racc = make_float4(0.f, 0.f, 0.f, 0.f);
    float wsum = 0.f;
    int nwarps = (gridDim.x * blockDim.x) >> 5;
    for (int nd = (blockIdx.x * blockDim.x + t) >> 5; nd < n; nd += nwarps) {
        float w = expf(g_pool_s[nd] - mx);
        if (lane == 0) wsum += w;
        float4 v = reinterpret_cast<const float4*>(g_h + (size_t)nd * D)[lane];
        racc.x += w * v.x; racc.y += w * v.y; racc.z += w * v.z; racc.w += w * v.w;
    }
    atomicAdd(&sacc[lane * 4 + 0], racc.x);
    atomicAdd(&sacc[lane * 4 + 1], racc.y);
    atomicAdd(&sacc[lane * 4 + 2], racc.z);
    atomicAdd(&sacc[lane * 4 + 3], racc.w);
    __syncthreads();
    if (t < D) atomicAdd(&g_hp[t], sacc[t]);
    if (lane == 0 && wsum != 0.f) atomicAdd(&g_sumw, wsum);
}

// ---------------- final head ----------------
__global__ void final_kernel(const float* __restrict__ rho_W, const float* __restrict__ rho_b,
                             const float* __restrict__ cls_W, const float* __restrict__ cls_b,
                             float* __restrict__ out)
{
    __shared__ float hp[D];
    __shared__ float hr[D];
    __shared__ float slog[4];
    int t = threadIdx.x;
    hp[t] = g_hp[t] / g_sumw;
    __syncthreads();
    float a = rho_b[t];
#pragma unroll 4
    for (int k = 0; k < D; k++) a += hp[k] * rho_W[k * D + t];
    hr[t] = a > 0.f ? a : 0.f;
    __syncthreads();
    if (t < 4) {
        float lg = cls_b[t];
#pragma unroll 4
        for (int d = 0; d < D; d++) lg += hr[d] * cls_W[d * 4 + t];
        slog[t] = lg;
    }
    __syncthreads();
    if (t == 0) {
        float hz[4], S[4];
        int am = 0;
        float best = slog[0];
        for (int c = 0; c < 4; c++) {
            hz[c] = 1.f / (1.f + expf(-slog[c]));
            if (slog[c] > best) { best = slog[c]; am = c; }
        }
        S[0] = 1.f - hz[0];
        for (int c = 1; c < 4; c++) S[c] = S[c - 1] * (1.f - hz[c]);
        for (int c = 0; c < 4; c++) out[c] = hz[c];
        for (int c = 0; c < 4; c++) out[4 + c] = S[c];
        out[8] = (float)am;
        for (int c = 0; c < 4; c++) out[9 + c] = slog[c];
    }
}

// ---------------- launch ----------------
extern "C" void kernel_launch(void* const* d_in, const int* in_sizes, int n_in,
                              void* d_out, int out_size)
{
    const float* x      = (const float*)d_in[0];
    const int*   ei     = (const int*)d_in[1];
    const float* emb_W  = (const float*)d_in[2];
    const float* emb_b  = (const float*)d_in[3];
    const float* ln1_g  = (const float*)d_in[4];
    const float* ln1_b  = (const float*)d_in[5];
    const float* gat_Wl = (const float*)d_in[6];
    const float* gat_bl = (const float*)d_in[7];
    const float* gat_Wr = (const float*)d_in[8];
    const float* gat_br = (const float*)d_in[9];
    const float* gat_att  = (const float*)d_in[10];
    const float* gat_bias = (const float*)d_in[11];
    const float* w1s[3] = {(const float*)d_in[12], (const float*)d_in[14], (const float*)d_in[16]};
    const float* w2s[3] = {(const float*)d_in[13], (const float*)d_in[15], (const float*)d_in[17]};
    const float* attn_Wa = (const float*)d_in[18];
    const float* attn_ba = (const float*)d_in[19];
    const float* attn_Wb = (const float*)d_in[20];
    const float* attn_bb = (const float*)d_in[21];
    const float* attn_Wc = (const float*)d_in[22];
    const float* attn_bc = (const float*)d_in[23];
    const float* rho_W   = (const float*)d_in[24];
    const float* rho_b   = (const float*)d_in[25];
    const float* cls_W   = (const float*)d_in[26];
    const float* cls_b   = (const float*)d_in[27];
    float* out = (float*)d_out;

    int n  = in_sizes[0] / 512;     // 50000
    int E  = in_sizes[1] / 2;       // 800000

    float*  p_h;   cudaGetSymbolAddress((void**)&p_h,   g_h);
    float*  p_hn;  cudaGetSymbolAddress((void**)&p_hn,  g_hn);
    __half* p_xl;  cudaGetSymbolAddress((void**)&p_xl,  g_xl);
    float*  p_xr;  cudaGetSymbolAddress((void**)&p_xr,  g_xr);
    float*  p_hid; cudaGetSymbolAddress((void**)&p_hid, g_hid);

    dim3 blk(256);
    int rowBlocks = (n + 127) / 128;
    int nBlocks   = (n + 255) / 256;
    int eBlocks   = (E + 255) / 256;
    int scanBlocks = (n + 255) / 256;

    // ---- CSR build ----
    csr_zero_kernel<<<nBlocks, blk>>>(n);
    csr_count_kernel<<<eBlocks, blk>>>(ei, E);
    scan1_kernel<<<scanBlocks, blk>>>(n);
    scan2_kernel<<<1, blk>>>(scanBlocks);
    scan3_kernel<<<nBlocks, blk>>>(n);
    csr_scatter_kernel<<<eBlocks, blk>>>(ei, E);

    // ---- embedding ----
    tgemm_kernel<<<dim3(rowBlocks, 1), blk>>>(x, emb_W, emb_b, p_h, n, 512, 128, ACT_RELU, 0, 0);

    int warpGrid = (n * 32 + 255) / 256;

    for (int i = 0; i < 3; i++) {
        ln_kernel<<<warpGrid, blk>>>(p_h, ln1_g + i * D, ln1_b + i * D, p_hn, n);
        // xl = hn@Wl+bl  -> fp16 output (halves gather traffic)
        tgemm_kernel<<<dim3(rowBlocks, 1), blk>>>(p_hn, gat_Wl + i * D * D, gat_bl + i * D,
                                                  (float*)p_xl, n, D, D, ACT_NONE, 0, 1);
        // xr = hn@Wr+br  -> fp32 (read once per node)
        tgemm_kernel<<<dim3(rowBlocks, 1), blk>>>(p_hn, gat_Wr + i * D * D, gat_br + i * D,
                                                  p_xr, n, D, D, ACT_NONE, 0, 0);

        gat_gather_kernel<<<warpGrid, blk>>>(p_xl, p_xr, gat_att + i * D, gat_bias + i * D, n);

        int H = D * (i + 1);
        tgemm_kernel<<<dim3(rowBlocks, H / 128), blk>>>(p_h, w1s[i], nullptr, p_hid, n, D, H, ACT_GELU, 0, 0);
        tgemm_kernel<<<dim3(rowBlocks, 1), blk>>>(p_hid, w2s[i], nullptr, p_h, n, H, D, ACT_NONE, 1, 0);
    }

    // ---- pooling: ta -> g_hn (fp32, free now), tb -> g_xr ----
    tgemm_kernel<<<dim3(rowBlocks, 1), blk>>>(p_h, attn_Wa, attn_ba, p_hn, n, D, D, ACT_TANH, 0, 0);
    tgemm_kernel<<<dim3(rowBlocks, 1), blk>>>(p_h, attn_Wb, attn_bb, p_xr, n, D, D, ACT_SIGM, 0, 0);

    init_pool_kernel<<<1, 128>>>();
    pool_score_kernel<<<warpGrid, blk>>>(p_hn, p_xr, attn_Wc, attn_bc, n);
    pool_max_kernel<<<160, blk>>>(n);
    pool_accum_kernel<<<296, blk>>>(n);
    final_kernel<<<1, 128>>>(rho_W, rho_b, cls_W, cls_b, out);

    (void)n_in; (void)out_size;
}

// round 15
// speedup vs baseline: 1.5349x; 1.1066x over previous
#include <cuda_runtime.h>
#include <math.h>
#include <stdint.h>

// ---------------- problem constants ----------------
#define NMAX 50000
#define EMAX 800000
#define D 128
#define HMAX 384

// ---------------- scratch (device globals; no mallocs allowed) ----------------
__device__ float g_h [NMAX * D];
__device__ float g_hn[NMAX * D];
__device__ float g_xl[NMAX * D];
__device__ float g_xr[NMAX * D];
__device__ float g_hid[NMAX * HMAX];
__device__ int   g_cnt[NMAX];
__device__ int   g_row[NMAX];
__device__ int   g_cur[NMAX];
__device__ int   g_csr_src[EMAX];
__device__ int   g_partial[256];
__device__ float g_pool_s[NMAX];
__device__ float g_hp[D];
__device__ float g_sumw;
__device__ unsigned g_maxu;

// ---------------- helpers ----------------
__device__ __forceinline__ unsigned fenc(float f) {
    unsigned b = __float_as_uint(f);
    return (b & 0x80000000u) ? ~b : (b | 0x80000000u);
}
__device__ __forceinline__ float fdec(unsigned u) {
    return __uint_as_float((u & 0x80000000u) ? (u & 0x7FFFFFFFu) : ~u);
}
__device__ __forceinline__ uint32_t f2tf(float f) {
    uint32_t u;
    asm("cvt.rna.tf32.f32 %0, %1;" : "=r"(u) : "f"(f));
    return u;
}
__device__ __forceinline__ void cp_async16(void* sdst, const void* gptr, bool pred) {
    uint32_t saddr = (uint32_t)__cvta_generic_to_shared(sdst);
    int sz = pred ? 16 : 0;
    asm volatile("cp.async.cg.shared.global [%0], [%1], 16, %2;"
                 :: "r"(saddr), "l"(gptr), "r"(sz));
}

#define ACT_NONE 0
#define ACT_RELU 1
#define ACT_GELU 2
#define ACT_TANH 3
#define ACT_SIGM 4

__device__ __forceinline__ float apply_act(float v, int act) {
    switch (act) {
        case ACT_RELU: return v > 0.f ? v : 0.f;
        case ACT_GELU: return 0.5f * v * (1.f + erff(v * 0.70710678118654752f));
        case ACT_TANH: return tanhf(v);
        case ACT_SIGM: return 1.f / (1.f + expf(-v));
        default: return v;
    }
}

// ---------------- CSR build (round-4 version: NO self loop in CSR) ----------------
__global__ void csr_zero_kernel(int n) {
    int i = blockIdx.x * blockDim.x + threadIdx.x;
    if (i < n) g_cnt[i] = 0;
}
__global__ void csr_count_kernel(const int* __restrict__ ei, int E) {
    int i = blockIdx.x * blockDim.x + threadIdx.x;
    if (i < E) atomicAdd(&g_cnt[ei[E + i]], 1);
}
__global__ void scan1_kernel(int n) {
    __shared__ int sm[256];
    int t = threadIdx.x;
    int i = blockIdx.x * 256 + t;
    int v = (i < n) ? g_cnt[i] : 0;
    sm[t] = v;
    __syncthreads();
#pragma unroll
    for (int off = 1; off < 256; off <<= 1) {
        int a = (t >= off) ? sm[t - off] : 0;
        __syncthreads();
        sm[t] += a;
        __syncthreads();
    }
    if (i < n) g_row[i] = sm[t] - v;   // exclusive
    if (t == 255) g_partial[blockIdx.x] = sm[255];
}
__global__ void scan2_kernel(int nb) {
    __shared__ int sm[256];
    int t = threadIdx.x;
    int v = (t < nb) ? g_partial[t] : 0;
    sm[t] = v;
    __syncthreads();
#pragma unroll
    for (int off = 1; off < 256; off <<= 1) {
        int a = (t >= off) ? sm[t - off] : 0;
        __syncthreads();
        sm[t] += a;
        __syncthreads();
    }
    if (t < nb) g_partial[t] = sm[t] - v;  // exclusive
}
__global__ void scan3_kernel(int n) {
    int i = blockIdx.x * blockDim.x + threadIdx.x;
    if (i < n) {
        int v = g_row[i] + g_partial[i >> 8];
        g_row[i] = v;
        g_cur[i] = v;
    }
}
__global__ void csr_scatter_kernel(const int* __restrict__ ei, int E) {
    int i = blockIdx.x * blockDim.x + threadIdx.x;
    if (i < E) {
        int d = ei[E + i];
        int slot = atomicAdd(&g_cur[d], 1);
        g_csr_src[slot] = ei[i];
    }
}

// ---------------- init ----------------
__global__ void init_pool_kernel() {
    int t = threadIdx.x;
    g_hp[t] = 0.f;
    if (t == 0) { g_sumw = 0.f; g_maxu = 0u; }
}

// ---------------- tf32 tensor-core GEMM, cp.async 2-stage pipeline, BK=16 ----------------
// Same 128x128 tile / warp layout / rna-rounded tf32 math as the 893us champion;
// only the load path changed (overlap next tile's global loads with current MMAs).
__global__ __launch_bounds__(256, 2)
void tgemm_kernel(const float* __restrict__ A, const float* __restrict__ B,
                  const float* __restrict__ bias, float* __restrict__ C,
                  int n, int K, int M, int act, int residual)
{
    __shared__ float sA[2][128][20];   // pad 20 -> 16B-aligned rows, conflict-free frag loads
    __shared__ float sB[2][16][136];   // pad 8

    int tid  = threadIdx.x;
    int lane = tid & 31;
    int warp = tid >> 5;
    int g    = lane >> 2;
    int tig  = lane & 3;
    int mW   = (warp & 3) * 32;
    int nW   = (warp >> 2) * 64;
    int rowBase = blockIdx.x * 128;
    int colBase = blockIdx.y * 128;

    float acc[2][8][4];
#pragma unroll
    for (int mt = 0; mt < 2; mt++)
#pragma unroll
        for (int nt = 0; nt < 8; nt++)
#pragma unroll
            for (int c = 0; c < 4; c++) acc[mt][nt][c] = 0.f;

    auto load_tile = [&](int st, int k0) {
        // A tile: 128 rows x 16 k = 512 x 16B chunks, 2 per thread
#pragma unroll
        for (int i = 0; i < 2; i++) {
            int idx = tid + 256 * i;
            int r   = idx >> 2;          // 4 chunks per row
            int kc  = (idx & 3) * 4;
            int gr  = rowBase + r;
            cp_async16(&sA[st][r][kc], A + (size_t)gr * K + k0 + kc, gr < n);
        }
        // B tile: 16 k x 128 cols = 512 x 16B chunks, 2 per thread
#pragma unroll
        for (int i = 0; i < 2; i++) {
            int idx = tid + 256 * i;
            int kr  = idx >> 5;          // 32 chunks per row
            int c   = (idx & 31) * 4;
            cp_async16(&sB[st][kr][c], B + (size_t)(k0 + kr) * M + colBase + c, true);
        }
        asm volatile("cp.async.commit_group;" ::: "memory");
    };

    int nIter = K >> 4;
    load_tile(0, 0);

    for (int it = 0; it < nIter; it++) {
        int st = it & 1;
        if (it + 1 < nIter) {
            load_tile((it + 1) & 1, (it + 1) << 4);
            asm volatile("cp.async.wait_group 1;" ::: "memory");
        } else {
            asm volatile("cp.async.wait_group 0;" ::: "memory");
        }
        __syncthreads();

#pragma unroll
        for (int kt = 0; kt < 2; kt++) {
            int kb = kt * 8;
            uint32_t a[2][4], b[8][2];
#pragma unroll
            for (int mt = 0; mt < 2; mt++) {
                int mb = mW + mt * 16;
                a[mt][0] = f2tf(sA[st][mb + g    ][kb + tig    ]);
                a[mt][1] = f2tf(sA[st][mb + g + 8][kb + tig    ]);
                a[mt][2] = f2tf(sA[st][mb + g    ][kb + tig + 4]);
                a[mt][3] = f2tf(sA[st][mb + g + 8][kb + tig + 4]);
            }
#pragma unroll
            for (int nt = 0; nt < 8; nt++) {
                int nb = nW + nt * 8;
                b[nt][0] = f2tf(sB[st][kb + tig    ][nb + g]);
                b[nt][1] = f2tf(sB[st][kb + tig + 4][nb + g]);
            }
#pragma unroll
            for (int mt = 0; mt < 2; mt++)
#pragma unroll
                for (int nt = 0; nt < 8; nt++) {
                    asm volatile(
                        "mma.sync.aligned.m16n8k8.row.col.f32.tf32.tf32.f32 "
                        "{%0,%1,%2,%3}, {%4,%5,%6,%7}, {%8,%9}, {%0,%1,%2,%3};"
                        : "+f"(acc[mt][nt][0]), "+f"(acc[mt][nt][1]),
                          "+f"(acc[mt][nt][2]), "+f"(acc[mt][nt][3])
                        : "r"(a[mt][0]), "r"(a[mt][1]), "r"(a[mt][2]), "r"(a[mt][3]),
                          "r"(b[nt][0]), "r"(b[nt][1]));
                }
        }
        __syncthreads();
    }

#pragma unroll
    for (int mt = 0; mt < 2; mt++) {
#pragma unroll
        for (int half = 0; half < 2; half++) {
            int gr = rowBase + mW + mt * 16 + g + half * 8;
            if (gr >= n) continue;
#pragma unroll
            for (int nt = 0; nt < 8; nt++) {
#pragma unroll
                for (int j = 0; j < 2; j++) {
                    int gc = colBase + nW + nt * 8 + tig * 2 + j;
                    float v = acc[mt][nt][half * 2 + j];
                    if (bias) v += bias[gc];
                    v = apply_act(v, act);
                    size_t o = (size_t)gr * M + gc;
                    if (residual) C[o] = C[o] + v; else C[o] = v;
                }
            }
        }
    }
}

// ---------------- LayerNorm (warp per row, float4) ----------------
__global__ void ln_kernel(const float* __restrict__ X, const float* __restrict__ g,
                          const float* __restrict__ b, float* __restrict__ Y, int n)
{
    int w = (blockIdx.x * blockDim.x + threadIdx.x) >> 5;
    int lane = threadIdx.x & 31;
    if (w >= n) return;
    float4 v = reinterpret_cast<const float4*>(X + (size_t)w * D)[lane];
    float s  = v.x + v.y + v.z + v.w;
    float s2 = v.x * v.x + v.y * v.y + v.z * v.z + v.w * v.w;
#pragma unroll
    for (int off = 16; off > 0; off >>= 1) {
        s  += __shfl_xor_sync(0xFFFFFFFFu, s,  off);
        s2 += __shfl_xor_sync(0xFFFFFFFFu, s2, off);
    }
    float mu = s * (1.f / 128.f);
    float var = s2 * (1.f / 128.f) - mu * mu;
    float rstd = rsqrtf(var + 1e-5f);
    float4 gg = reinterpret_cast<const float4*>(g)[lane];
    float4 bb = reinterpret_cast<const float4*>(b)[lane];
    float4 o;
    o.x = (v.x - mu) * rstd * gg.x + bb.x;
    o.y = (v.y - mu) * rstd * gg.y + bb.y;
    o.z = (v.z - mu) * rstd * gg.z + bb.z;
    o.w = (v.w - mu) * rstd * gg.w + bb.w;
    reinterpret_cast<float4*>(Y + (size_t)w * D)[lane] = o;
}

// ---------------- GATv2 fused: warp per node, online softmax, no atomics (R4 body) ----------------
__global__ void gat_gather_kernel(const float* __restrict__ xl, const float* __restrict__ xr,
                                  const float* __restrict__ att, const float* __restrict__ bias,
                                  int n)
{
    int node = (blockIdx.x * blockDim.x + threadIdx.x) >> 5;
    int lane = threadIdx.x & 31;
    if (node >= n) return;

    float4 at4 = reinterpret_cast<const float4*>(att)[lane];
    float4 xr4 = reinterpret_cast<const float4*>(xr + (size_t)node * D)[lane];

    // self loop first (appended self loops in reference)
    float4 v4 = reinterpret_cast<const float4*>(xl + (size_t)node * D)[lane];
    float ex, ey, ez, ew, sc;
    {
        ex = v4.x + xr4.x; ex = ex > 0.f ? ex : 0.2f * ex;
        ey = v4.y + xr4.y; ey = ey > 0.f ? ey : 0.2f * ey;
        ez = v4.z + xr4.z; ez = ez > 0.f ? ez : 0.2f * ez;
        ew = v4.w + xr4.w; ew = ew > 0.f ? ew : 0.2f * ew;
        sc = ex * at4.x + ey * at4.y + ez * at4.z + ew * at4.w;
#pragma unroll
        for (int off = 16; off > 0; off >>= 1) sc += __shfl_xor_sync(0xFFFFFFFFu, sc, off);
    }
    float m = sc;
    float den = 1.f;
    float4 acc = v4;   // weight exp(sc - m) = 1

    int beg = g_row[node];
    int end = beg + g_cnt[node];
    for (int j = beg; j < end; j++) {
        int s = g_csr_src[j];
        v4 = reinterpret_cast<const float4*>(xl + (size_t)s * D)[lane];
        ex = v4.x + xr4.x; ex = ex > 0.f ? ex : 0.2f * ex;
        ey = v4.y + xr4.y; ey = ey > 0.f ? ey : 0.2f * ey;
        ez = v4.z + xr4.z; ez = ez > 0.f ? ez : 0.2f * ez;
        ew = v4.w + xr4.w; ew = ew > 0.f ? ew : 0.2f * ew;
        sc = ex * at4.x + ey * at4.y + ez * at4.z + ew * at4.w;
#pragma unroll
        for (int off = 16; off > 0; off >>= 1) sc += __shfl_xor_sync(0xFFFFFFFFu, sc, off);
        if (sc > m) {
            float f = expf(m - sc);
            den *= f;
            acc.x *= f; acc.y *= f; acc.z *= f; acc.w *= f;
            m = sc;
        }
        float w = expf(sc - m);
        den += w;
        acc.x += w * v4.x; acc.y += w * v4.y; acc.z += w * v4.z; acc.w += w * v4.w;
    }

    float inv = 1.f / den;
    float4 bb = reinterpret_cast<const float4*>(bias)[lane];
    float4* hp = reinterpret_cast<float4*>(g_h + (size_t)node * D);
    float4 h = hp[lane];
    h.x += acc.x * inv + bb.x;
    h.y += acc.y * inv + bb.y;
    h.z += acc.z * inv + bb.z;
    h.w += acc.w * inv + bb.w;
    hp[lane] = h;
}

// ---------------- pooling ----------------
__global__ void pool_score_kernel(const float* __restrict__ ta, const float* __restrict__ tb,
                                  const float* __restrict__ Wc, const float* __restrict__ bc, int n)
{
    int w = (blockIdx.x * blockDim.x + threadIdx.x) >> 5;
    int lane = threadIdx.x & 31;
    if (w >= n) return;
    float4 a = reinterpret_cast<const float4*>(ta + (size_t)w * D)[lane];
    float4 b = reinterpret_cast<const float4*>(tb + (size_t)w * D)[lane];
    float4 c = reinterpret_cast<const float4*>(Wc)[lane];
    float acc = a.x * b.x * c.x + a.y * b.y * c.y + a.z * b.z * c.z + a.w * b.w * c.w;
#pragma unroll
    for (int off = 16; off > 0; off >>= 1) acc += __shfl_xor_sync(0xFFFFFFFFu, acc, off);
    if (lane == 0) g_pool_s[w] = acc + bc[0];
}

__global__ void pool_max_kernel(int n)
{
    __shared__ float sm[256];
    int t = threadIdx.x;
    float m = -1e30f;
    for (int i = blockIdx.x * blockDim.x + t; i < n; i += gridDim.x * blockDim.x)
        m = fmaxf(m, g_pool_s[i]);
    sm[t] = m;
    __syncthreads();
    for (int s = 128; s > 0; s >>= 1) {
        if (t < s) sm[t] = fmaxf(sm[t], sm[t + s]);
        __syncthreads();
    }
    if (t == 0) atomicMax(&g_maxu, fenc(sm[0]));
}

__global__ void pool_accum_kernel(int n)
{
    __shared__ float sacc[D];
    int t = threadIdx.x;
    int lane = t & 31;
    if (t < D) sacc[t] = 0.f;
    __syncthreads();
    float mx = fdec(g_maxu);
    float4 racc = make_float4(0.f, 0.f, 0.f, 0.f);
    float wsum = 0.f;
    int nwarps = (gridDim.x * blockDim.x) >> 5;
    for (int nd = (blockIdx.x * blockDim.x + t) >> 5; nd < n; nd += nwarps) {
        float w = expf(g_pool_s[nd] - mx);
        if (lane == 0) wsum += w;
        float4 v = reinterpret_cast<const float4*>(g_h + (size_t)nd * D)[lane];
        racc.x += w * v.x; racc.y += w * v.y; racc.z += w * v.z; racc.w += w * v.w;
    }
    atomicAdd(&sacc[lane * 4 + 0], racc.x);
    atomicAdd(&sacc[lane * 4 + 1], racc.y);
    atomicAdd(&sacc[lane * 4 + 2], racc.z);
    atomicAdd(&sacc[lane * 4 + 3], racc.w);
    __syncthreads();
    if (t < D) atomicAdd(&g_hp[t], sacc[t]);
    if (lane == 0 && wsum != 0.f) atomicAdd(&g_sumw, wsum);
}

// ---------------- final head ----------------
__global__ void final_kernel(const float* __restrict__ rho_W, const float* __restrict__ rho_b,
                             const float* __restrict__ cls_W, const float* __restrict__ cls_b,
                             float* __restrict__ out)
{
    __shared__ float hp[D];
    __shared__ float hr[D];
    __shared__ float slog[4];
    int t = threadIdx.x;
    hp[t] = g_hp[t] / g_sumw;
    __syncthreads();
    float a = rho_b[t];
#pragma unroll 4
    for (int k = 0; k < D; k++) a += hp[k] * rho_W[k * D + t];
    hr[t] = a > 0.f ? a : 0.f;
    __syncthreads();
    if (t < 4) {
        float lg = cls_b[t];
#pragma unroll 4
        for (int d = 0; d < D; d++) lg += hr[d] * cls_W[d * 4 + t];
        slog[t] = lg;
    }
    __syncthreads();
    if (t == 0) {
        float hz[4], S[4];
        int am = 0;
        float best = slog[0];
        for (int c = 0; c < 4; c++) {
            hz[c] = 1.f / (1.f + expf(-slog[c]));
            if (slog[c] > best) { best = slog[c]; am = c; }
        }
        S[0] = 1.f - hz[0];
        for (int c = 1; c < 4; c++) S[c] = S[c - 1] * (1.f - hz[c]);
        for (int c = 0; c < 4; c++) out[c] = hz[c];
        for (int c = 0; c < 4; c++) out[4 + c] = S[c];
        out[8] = (float)am;
        for (int c = 0; c < 4; c++) out[9 + c] = slog[c];
    }
}

// ---------------- launch ----------------
extern "C" void kernel_launch(void* const* d_in, const int* in_sizes, int n_in,
                              void* d_out, int out_size)
{
    const float* x      = (const float*)d_in[0];
    const int*   ei     = (const int*)d_in[1];
    const float* emb_W  = (const float*)d_in[2];
    const float* emb_b  = (const float*)d_in[3];
    const float* ln1_g  = (const float*)d_in[4];
    const float* ln1_b  = (const float*)d_in[5];
    const float* gat_Wl = (const float*)d_in[6];
    const float* gat_bl = (const float*)d_in[7];
    const float* gat_Wr = (const float*)d_in[8];
    const float* gat_br = (const float*)d_in[9];
    const float* gat_att  = (const float*)d_in[10];
    const float* gat_bias = (const float*)d_in[11];
    const float* w1s[3] = {(const float*)d_in[12], (const float*)d_in[14], (const float*)d_in[16]};
    const float* w2s[3] = {(const float*)d_in[13], (const float*)d_in[15], (const float*)d_in[17]};
    const float* attn_Wa = (const float*)d_in[18];
    const float* attn_ba = (const float*)d_in[19];
    const float* attn_Wb = (const float*)d_in[20];
    const float* attn_bb = (const float*)d_in[21];
    const float* attn_Wc = (const float*)d_in[22];
    const float* attn_bc = (const float*)d_in[23];
    const float* rho_W   = (const float*)d_in[24];
    const float* rho_b   = (const float*)d_in[25];
    const float* cls_W   = (const float*)d_in[26];
    const float* cls_b   = (const float*)d_in[27];
    float* out = (float*)d_out;

    int n  = in_sizes[0] / 512;     // 50000
    int E  = in_sizes[1] / 2;       // 800000

    float* p_h;    cudaGetSymbolAddress((void**)&p_h,    g_h);
    float* p_hn;   cudaGetSymbolAddress((void**)&p_hn,   g_hn);
    float* p_xl;   cudaGetSymbolAddress((void**)&p_xl,   g_xl);
    float* p_xr;   cudaGetSymbolAddress((void**)&p_xr,   g_xr);
    float* p_hid;  cudaGetSymbolAddress((void**)&p_hid,  g_hid);

    dim3 blk(256);
    int rowBlocks = (n + 127) / 128;
    int nBlocks   = (n + 255) / 256;
    int eBlocks   = (E + 255) / 256;
    int scanBlocks = (n + 255) / 256;

    // ---- CSR build ----
    csr_zero_kernel<<<nBlocks, blk>>>(n);
    csr_count_kernel<<<eBlocks, blk>>>(ei, E);
    scan1_kernel<<<scanBlocks, blk>>>(n);
    scan2_kernel<<<1, blk>>>(scanBlocks);
    scan3_kernel<<<nBlocks, blk>>>(n);
    csr_scatter_kernel<<<eBlocks, blk>>>(ei, E);

    // ---- embedding ----
    tgemm_kernel<<<dim3(rowBlocks, 1), blk>>>(x, emb_W, emb_b, p_h, n, 512, 128, ACT_RELU, 0);

    int warpGrid = (n * 32 + 255) / 256;

    for (int i = 0; i < 3; i++) {
        ln_kernel<<<warpGrid, blk>>>(p_h, ln1_g + i * D, ln1_b + i * D, p_hn, n);
        tgemm_kernel<<<dim3(rowBlocks, 1), blk>>>(p_hn, gat_Wl + i * D * D, gat_bl + i * D, p_xl, n, D, D, ACT_NONE, 0);
        tgemm_kernel<<<dim3(rowBlocks, 1), blk>>>(p_hn, gat_Wr + i * D * D, gat_br + i * D, p_xr, n, D, D, ACT_NONE, 0);

        gat_gather_kernel<<<warpGrid, blk>>>(p_xl, p_xr, gat_att + i * D, gat_bias + i * D, n);

        int H = D * (i + 1);
        tgemm_kernel<<<dim3(rowBlocks, H / 128), blk>>>(p_h, w1s[i], nullptr, p_hid, n, D, H, ACT_GELU, 0);
        tgemm_kernel<<<dim3(rowBlocks, 1), blk>>>(p_hid, w2s[i], nullptr, p_h, n, H, D, ACT_NONE, 1);
    }

    // ---- pooling ----
    tgemm_kernel<<<dim3(rowBlocks, 1), blk>>>(p_h, attn_Wa, attn_ba, p_xl, n, D, D, ACT_TANH, 0);
    tgemm_kernel<<<dim3(rowBlocks, 1), blk>>>(p_h, attn_Wb, attn_bb, p_xr, n, D, D, ACT_SIGM, 0);

    init_pool_kernel<<<1, 128>>>();
    pool_score_kernel<<<warpGrid, blk>>>(p_xl, p_xr, attn_Wc, attn_bc, n);
    pool_max_kernel<<<160, blk>>>(n);
    pool_accum_kernel<<<296, blk>>>(n);
    final_kernel<<<1, 128>>>(rho_W, rho_b, cls_W, cls_b, out);

    (void)n_in; (void)out_size;
}